// round 9
// baseline (speedup 1.0000x reference)
#include <cuda_runtime.h>
#include <cuda_bf16.h>
#include <cstdint>

// MaxUnpooling2D scatter-add.
//   updates/mask: [B=16, H=128, W=128, C=64]  -> 16,777,216 elements
//   output:       [B=16, OH=256, OW=256, C=64] -> 67,108,864 floats (268 MB)
// out_idx = (b<<22) | (mask & ~63) | c   (channel comes from the source element)
//
// R9: GROUP=2 phased pipeline; zero pass for group g+1 done via
// cp.async.bulk (TMA-path, zero LSU cost) from blocks placed FIRST in the
// grid so the bulk stores drain concurrently with the 2048 scatter blocks
// (R8 had them last -> exposed serial tail -> regression). Input loads use
// __ldcs (evict-first) so 16 MB/group of streaming input doesn't evict the
// L2-resident scatter-target lines.

static constexpr int B_DIM      = 16;
static constexpr int GROUP      = 2;
static constexpr int NGROUPS    = B_DIM / GROUP;              // 8
static constexpr int HWC        = 1 << 20;                    // elems per batch
static constexpr int OUT_PER_B  = 1 << 22;                    // out floats per batch

static constexpr int THREADS    = 256;

static constexpr int SQ_PER_B   = HWC / 4;                    // 262,144 quads (1<<18)
static constexpr int SQ_PER_G   = GROUP * SQ_PER_B;           // 524,288 quads
static constexpr int S_BLOCKS   = SQ_PER_G / THREADS;         // 2048

// Zero pass via bulk copies: 33,554,432 bytes per group.
static constexpr int ZCHUNK     = 16384;                      // bytes per bulk op (smem buf)
static constexpr int ZOPS       = 8;                          // ops per zero block
static constexpr int ZB_BLOCKS  = (GROUP * OUT_PER_B * 4) / (ZCHUNK * ZOPS);  // 256
static_assert(ZB_BLOCKS * ZOPS * ZCHUNK == GROUP * OUT_PER_B * 4, "cover");

static constexpr int FUSED_BLOCKS = ZB_BLOCKS + S_BLOCKS;     // 2304

// ---------------------------------------------------------------------------
__device__ __forceinline__ uint32_t smem_u32(const void* p)
{
    uint32_t a;
    asm("{ .reg .u64 t; cvta.to.shared.u64 t, %1; cvt.u32.u64 %0, t; }"
        : "=r"(a) : "l"(p));
    return a;
}

// Scatter one group (2 batches). Pointers pre-offset to group start.
// Streaming loads (evict-first) keep L2 for the atomic target lines.
__device__ __forceinline__ void scatter_group(const float4* __restrict__ upd4,
                                              const int4*   __restrict__ msk4,
                                              float* __restrict__ out,
                                              int sblk)
{
    int q  = sblk * THREADS + threadIdx.x;  // quad index in group
    int i  = q << 2;                        // element index in group
    int bl = q >> 18;                       // batch within group (SQ_PER_B = 1<<18)
    int c  = i & 63;                        // channel of first lane

    float4 u = __ldcs(&upd4[q]);            // streaming: single use
    int4   m = __ldcs(&msk4[q]);

    int base = bl << 22;                    // batch-local output offset

    atomicAdd(&out[base | (m.x & ~63) | (c + 0)], u.x);
    atomicAdd(&out[base | (m.y & ~63) | (c + 1)], u.y);
    atomicAdd(&out[base | (m.z & ~63) | (c + 2)], u.z);
    atomicAdd(&out[base | (m.w & ~63) | (c + 3)], u.w);
}

// ---------------------------------------------------------------------------
// Fused kernel. Block roles:
//   blk in [0, ZB_BLOCKS)            -> bulk-zero group g+1 (issued FIRST,
//                                       drains async during scatter)
//   blk in [ZB_BLOCKS, FUSED_BLOCKS) -> scatter group g
__global__ void __launch_bounds__(THREADS)
scatter_zero_kernel(const float4* __restrict__ upd4,
                    const int4*   __restrict__ msk4,
                    float* __restrict__ out_g,
                    char*  __restrict__ out_next_bytes)
{
    __shared__ __align__(128) char zbuf[ZCHUNK];

    int blk = blockIdx.x;
    if (blk >= ZB_BLOCKS) {
        scatter_group(upd4, msk4, out_g, blk - ZB_BLOCKS);
        return;
    }

    // --- zero path (first wave) ---
    // Zero the smem staging buffer: 1024 float4 / 256 threads = 4 each.
    float4* z4 = (float4*)zbuf;
    const float4 z = make_float4(0.f, 0.f, 0.f, 0.f);
    #pragma unroll
    for (int k = 0; k < ZCHUNK / 16 / THREADS; k++)
        z4[k * THREADS + threadIdx.x] = z;
    __syncthreads();

    // Make generic-proxy smem writes visible to the async proxy.
    asm volatile("fence.proxy.async.shared::cta;" ::: "memory");

    if (threadIdx.x == 0) {
        uint32_t src = smem_u32(zbuf);
        char* dst0 = out_next_bytes + (size_t)blk * (ZOPS * ZCHUNK);
        #pragma unroll
        for (int k = 0; k < ZOPS; k++) {
            asm volatile(
                "cp.async.bulk.global.shared::cta.bulk_group [%0], [%1], %2;"
                :: "l"(dst0 + (size_t)k * ZCHUNK), "r"(src), "n"(ZCHUNK)
                : "memory");
        }
        asm volatile("cp.async.bulk.commit_group;" ::: "memory");
        // Must complete before block exit so the next kernel (scatter g+1)
        // is ordered after these stores. Overlaps with scatter blocks chip-wide.
        asm volatile("cp.async.bulk.wait_group 0;" ::: "memory");
    }
}

// Epilogue: scatter only (last group).
__global__ void __launch_bounds__(THREADS)
scatter_kernel(const float4* __restrict__ upd4,
               const int4*   __restrict__ msk4,
               float* __restrict__ out_g)
{
    scatter_group(upd4, msk4, out_g, blockIdx.x);
}

// ---------------------------------------------------------------------------
extern "C" void kernel_launch(void* const* d_in, const int* in_sizes, int n_in,
                              void* d_out, int out_size)
{
    const float4* upd4 = (const float4*)d_in[0];
    const int4*   msk4 = (const int4*)d_in[1];
    float*        out  = (float*)d_out;

    const size_t GRP_QUADS = (size_t)SQ_PER_G;            // input quads per group
    const size_t GRP_OUT   = (size_t)GROUP * OUT_PER_B;   // output floats per group

    // Prologue: zero group 0 (graph-capturable memset node).
    cudaMemsetAsync(out, 0, GRP_OUT * sizeof(float), 0);

    // Steady state: bulk-zero(g+1) [first wave] + scatter(g).
    for (int g = 0; g < NGROUPS - 1; g++) {
        scatter_zero_kernel<<<FUSED_BLOCKS, THREADS>>>(
            upd4 + (size_t)g * GRP_QUADS,
            msk4 + (size_t)g * GRP_QUADS,
            out  + (size_t)g * GRP_OUT,
            (char*)(out + (size_t)(g + 1) * GRP_OUT));
    }

    // Epilogue: scatter last group.
    int g = NGROUPS - 1;
    scatter_kernel<<<S_BLOCKS, THREADS>>>(
        upd4 + (size_t)g * GRP_QUADS,
        msk4 + (size_t)g * GRP_QUADS,
        out  + (size_t)g * GRP_OUT);
}

// round 10
// speedup vs baseline: 1.3147x; 1.3147x over previous
#include <cuda_runtime.h>
#include <cuda_bf16.h>
#include <cstdint>

// MaxUnpooling2D scatter-add.
//   updates/mask: [B=16, H=128, W=128, C=64]  -> 16,777,216 elements
//   output:       [B=16, OH=256, OW=256, C=64] -> 67,108,864 floats (268 MB)
// out_idx = (b<<22) | (mask & ~63) | c   (channel comes from the source element)
//
// R10: R6's proven recipe (GROUP=2, phased zero->scatter, scatter blocks
// first, 1 quad/thread scatter, 1 float4/thread STG zero, 9 launches),
// with ONE change: __ldcs (evict-first) on the streaming input loads so the
// 16 MB/group of single-use updates+mask doesn't evict the 33.5 MB
// L2-resident scatter-target set.

static constexpr int B_DIM      = 16;
static constexpr int GROUP      = 2;
static constexpr int NGROUPS    = B_DIM / GROUP;              // 8
static constexpr int HWC        = 1 << 20;                    // elems per batch
static constexpr int OUT_PER_B  = 1 << 22;                    // out floats per batch

static constexpr int THREADS    = 256;

static constexpr int SQ_PER_B   = HWC / 4;                    // 262,144 quads (1<<18)
static constexpr int SQ_PER_G   = GROUP * SQ_PER_B;           // 524,288 quads
static constexpr int S_BLOCKS   = SQ_PER_G / THREADS;         // 2048

static constexpr int ZV_PER_G   = GROUP * OUT_PER_B / 4;      // 2,097,152 float4
static constexpr int Z_BLOCKS   = ZV_PER_G / THREADS;         // 8192

// ---------------------------------------------------------------------------
// Scatter one group (2 batches). Pointers pre-offset to group start.
// One quad (4 consecutive channels) per thread — minimal registers.
// __ldcs: inputs are single-use streaming; keep L2 for the atomic targets.
__device__ __forceinline__ void scatter_group(const float4* __restrict__ upd4,
                                              const int4*   __restrict__ msk4,
                                              float* __restrict__ out,
                                              int sblk)
{
    int q  = sblk * THREADS + threadIdx.x;  // quad index in group, 0 .. 524,287
    int i  = q << 2;                        // element index in group
    int bl = q >> 18;                       // batch within group (SQ_PER_B = 1<<18)
    int c  = i & 63;                        // channel of first lane

    float4 u = __ldcs(&upd4[q]);
    int4   m = __ldcs(&msk4[q]);

    int base = bl << 22;                    // batch-local output offset

    atomicAdd(&out[base | (m.x & ~63) | (c + 0)], u.x);
    atomicAdd(&out[base | (m.y & ~63) | (c + 1)], u.y);
    atomicAdd(&out[base | (m.z & ~63) | (c + 2)], u.z);
    atomicAdd(&out[base | (m.w & ~63) | (c + 3)], u.w);
}

__device__ __forceinline__ void zero_group(float4* __restrict__ out4, int zblk)
{
    out4[zblk * THREADS + threadIdx.x] = make_float4(0.f, 0.f, 0.f, 0.f);
}

// ---------------------------------------------------------------------------
__global__ void __launch_bounds__(THREADS)
zero_kernel(float4* __restrict__ out4)
{
    zero_group(out4, blockIdx.x);
}

// Fused: scatter group g (blocks [0, S_BLOCKS)) then zero group g+1
// (blocks [S_BLOCKS, S_BLOCKS+Z_BLOCKS)). Scatter-first block order.
__global__ void __launch_bounds__(THREADS)
scatter_zero_kernel(const float4* __restrict__ upd4,
                    const int4*   __restrict__ msk4,
                    float* __restrict__ out_g,
                    float4* __restrict__ out4_next)
{
    int blk = blockIdx.x;
    if (blk < S_BLOCKS) {
        scatter_group(upd4, msk4, out_g, blk);
    } else {
        zero_group(out4_next, blk - S_BLOCKS);
    }
}

__global__ void __launch_bounds__(THREADS)
scatter_kernel(const float4* __restrict__ upd4,
               const int4*   __restrict__ msk4,
               float* __restrict__ out_g)
{
    scatter_group(upd4, msk4, out_g, blockIdx.x);
}

// ---------------------------------------------------------------------------
extern "C" void kernel_launch(void* const* d_in, const int* in_sizes, int n_in,
                              void* d_out, int out_size)
{
    const float4* upd4 = (const float4*)d_in[0];
    const int4*   msk4 = (const int4*)d_in[1];
    float*        out  = (float*)d_out;

    const size_t GRP_QUADS = (size_t)SQ_PER_G;                 // input quads per group
    const size_t GRP_OUT   = (size_t)GROUP * OUT_PER_B;        // output floats per group

    // Prologue: zero group 0.
    zero_kernel<<<Z_BLOCKS, THREADS>>>((float4*)out);

    // Steady state: scatter(g) then zero(g+1), phased by block order.
    for (int g = 0; g < NGROUPS - 1; g++) {
        scatter_zero_kernel<<<S_BLOCKS + Z_BLOCKS, THREADS>>>(
            upd4 + (size_t)g * GRP_QUADS,
            msk4 + (size_t)g * GRP_QUADS,
            out  + (size_t)g * GRP_OUT,
            (float4*)(out + (size_t)(g + 1) * GRP_OUT));
    }

    // Epilogue: scatter last group.
    int g = NGROUPS - 1;
    scatter_kernel<<<S_BLOCKS, THREADS>>>(
        upd4 + (size_t)g * GRP_QUADS,
        msk4 + (size_t)g * GRP_QUADS,
        out  + (size_t)g * GRP_OUT);
}